// round 13
// baseline (speedup 1.0000x reference)
#include <cuda_runtime.h>
#include <cuda_bf16.h>
#include <cstdint>

#define NB 64
#define TB 1024
#define IB 88
#define HB 1024

#define NCTA 128        // 4 batch-quarters x 32 col-groups
#define NMW 16          // mma warps
#define RT2 544         // 16 mma warps + 1 control warp

// smem byte offsets
#define SM_W    0        // W hi frag-packed 64KB, then W lo 64KB
#define SM_A    131072   // A hi 32KB, A lo 32KB
#define SM_RED  196608   // 16 warps * 512 floats = 32KB
#define SM_MBAR 229376   // 4 chunk mbarriers
#define SM_TOT  229440

// device scratch
__device__ __align__(256)  float g_ih[(size_t)NB * TB * HB];
// A-operand images, mma-fragment order: [buf][hi/lo][quarter][ktile 64][lane 32][reg 4] u32
__device__ __align__(1024) unsigned char g_ha[2][2][4][32768];
__device__ unsigned g_arrive, g_epoch;

// ---- ptx helpers (baseline PTX only; no 'a' features) ----
__device__ __forceinline__ void mbinit(uint32_t m, uint32_t c) {
    asm volatile("mbarrier.init.shared.b64 [%0], %1;" :: "r"(m), "r"(c) : "memory");
}
__device__ __forceinline__ void mbexpect(uint32_t m, uint32_t b) {
    asm volatile("mbarrier.arrive.expect_tx.shared.b64 _, [%0], %1;" :: "r"(m), "r"(b) : "memory");
}
__device__ __forceinline__ void mwait(uint32_t m, uint32_t par) {
    asm volatile(
        "{\n\t.reg .pred P;\n"
        "W%=:\n\t"
        "mbarrier.try_wait.parity.shared::cta.b64 P, [%0], %1, 0x989680;\n\t"
        "@P bra D%=;\n\t"
        "bra W%=;\n"
        "D%=:\n\t}" :: "r"(m), "r"(par) : "memory");
}
__device__ __forceinline__ void bulkcp8k(uint32_t dst, const void* src, uint32_t mbar) {
    asm volatile(
        "cp.async.bulk.shared::cluster.global.mbarrier::complete_tx::bytes [%0], [%1], %2, [%3];"
        :: "r"(dst), "l"(src), "r"(8192u), "r"(mbar) : "memory");
}
__device__ __forceinline__ void gbar(unsigned b) {
    unsigned old;
    asm volatile("atom.release.gpu.global.add.u32 %0, [%1], 1;"
                 : "=r"(old) : "l"(&g_arrive) : "memory");
    if (old + 1u == b * (unsigned)NCTA) {
        asm volatile("st.release.gpu.global.u32 [%0], %1;" :: "l"(&g_epoch), "r"(b) : "memory");
    } else {
        unsigned e;
        do {
            asm volatile("ld.acquire.gpu.global.u32 %0, [%1];" : "=r"(e) : "l"(&g_epoch) : "memory");
        } while (e < b);
    }
}
__device__ __forceinline__ void mma16816(float c[4], const uint32_t a[4], uint32_t b0, uint32_t b1) {
    asm volatile(
        "mma.sync.aligned.m16n8k16.row.col.f32.bf16.bf16.f32 "
        "{%0,%1,%2,%3}, {%4,%5,%6,%7}, {%8,%9}, {%0,%1,%2,%3};"
        : "+f"(c[0]), "+f"(c[1]), "+f"(c[2]), "+f"(c[3])
        : "r"(a[0]), "r"(a[1]), "r"(a[2]), "r"(a[3]), "r"(b0), "r"(b1));
}

// ---- kernel 1: ih = x @ W_ih^T + b (fp32 SIMT); also resets barrier state ----
__global__ __launch_bounds__(256) void ih_kernel(const float* __restrict__ x,
                                                 const float* __restrict__ W_ih,
                                                 const float* __restrict__ b_ih) {
    if (blockIdx.x == 0 && blockIdx.y == 0 && threadIdx.x == 0) {
        g_arrive = 0u; g_epoch = 0u;
    }
    extern __shared__ float smf[];
    float* xs = smf;
    float* wt = smf + IB * 64;
    const int jb = blockIdx.x * 128, mb = blockIdx.y * 64, tid = threadIdx.x;
    for (int e = tid; e < 64 * IB; e += 256) {
        int m = e / IB, i = e - m * IB;
        xs[i * 64 + m] = x[(size_t)(mb + m) * IB + i];
    }
    for (int e = tid; e < 128 * IB; e += 256) {
        int j = e / IB, i = e - j * IB;
        wt[i * 128 + j] = W_ih[(size_t)(jb + j) * IB + i];
    }
    __syncthreads();
    const int jo = (tid & 15) * 8, mo = (tid >> 4) * 4;
    float acc[4][8];
#pragma unroll
    for (int jj = 0; jj < 8; jj++) {
        float b = b_ih[jb + jo + jj];
        acc[0][jj] = b; acc[1][jj] = b; acc[2][jj] = b; acc[3][jj] = b;
    }
#pragma unroll 4
    for (int i = 0; i < IB; i++) {
        float4 xv = *(const float4*)&xs[i * 64 + mo];
        float4 w0 = *(const float4*)&wt[i * 128 + jo];
        float4 w1 = *(const float4*)&wt[i * 128 + jo + 4];
        float xm[4] = {xv.x, xv.y, xv.z, xv.w};
#pragma unroll
        for (int mm = 0; mm < 4; mm++) {
            acc[mm][0] += xm[mm] * w0.x; acc[mm][1] += xm[mm] * w0.y;
            acc[mm][2] += xm[mm] * w0.z; acc[mm][3] += xm[mm] * w0.w;
            acc[mm][4] += xm[mm] * w1.x; acc[mm][5] += xm[mm] * w1.y;
            acc[mm][6] += xm[mm] * w1.z; acc[mm][7] += xm[mm] * w1.w;
        }
    }
#pragma unroll
    for (int mm = 0; mm < 4; mm++) {
        size_t row = (size_t)(mb + mo + mm) * HB + jb + jo;
        *(float4*)&g_ih[row]     = make_float4(acc[mm][0], acc[mm][1], acc[mm][2], acc[mm][3]);
        *(float4*)&g_ih[row + 4] = make_float4(acc[mm][4], acc[mm][5], acc[mm][6], acc[mm][7]);
    }
}

// ---- persistent split-bf16 HMMA recurrence (R7 structure, 16 mma warps) ----
// CTA (q,g): batch rows q*16..+15, hidden cols g*32..+31.
// Warp w (<16) owns k in [w*64, w*64+64) (4 ktiles) x ALL 4 n-tiles.
// B-hi in registers; B-lo from smem; A staged by bulk copy (4 chunks).
// warp 16 = control: global-counter barrier + copies.
__global__ __launch_bounds__(RT2, 1)
void rnn_kernel(const float* __restrict__ initial, const float* __restrict__ W_hh,
                float* __restrict__ out, int two) {
    extern __shared__ __align__(1024) unsigned char sm[];
    const uint32_t smb = (uint32_t)__cvta_generic_to_shared(sm);
    const int tid = threadIdx.x, wid = tid >> 5, lane = tid & 31;
    const int bid = blockIdx.x;
    const int q = bid >> 5, g = bid & 31, jb = g * 32;
    float* red = (float*)(sm + SM_RED);
    const uint32_t mb0 = smb + SM_MBAR;
    const size_t NTH = (size_t)NB * TB * HB;

    if (tid == 0)
        for (int ch = 0; ch < 4; ch++) mbinit(mb0 + ch * 8, 1);

    // stage W slice, fragment-packed (hi at SM_W, lo at +64KB)
    for (int e = tid; e < 32 * HB; e += RT2) {
        int n = e >> 10, k = e & (HB - 1);
        float w = W_hh[(size_t)(jb + n) * HB + k];
        __nv_bfloat16 hv = __float2bfloat16(w);
        __nv_bfloat16 lv = __float2bfloat16(w - __bfloat162float(hv));
        int nt = n >> 3, nn = n & 7, kt = k >> 4, kk = k & 15;
        int lf = nn * 4 + ((kk >> 1) & 3);
        uint32_t off = (uint32_t)(((nt * 64 + kt) * 32 + lf) * 8 + (kk >> 3) * 4 + (kk & 1) * 2);
        *(unsigned short*)(sm + SM_W + off)         = __bfloat16_as_ushort(hv);
        *(unsigned short*)(sm + SM_W + 65536 + off) = __bfloat16_as_ushort(lv);
    }

    // ---- step 0: h0 = initial + ih[:,0]; emit out + A image buf0 ----
    for (int e = tid; e < 512; e += RT2) {
        int row = e >> 5, j = e & 31, jg = jb + j, n0 = q * 16 + row;
        float v = initial[(size_t)n0 * HB + jg] + g_ih[(size_t)n0 * TB * HB + jg];
        out[(size_t)n0 * TB * HB + jg] = v;
        if (two) out[NTH + (size_t)n0 * TB * HB + jg] = v;
        __nv_bfloat16 hv = __float2bfloat16(v);
        __nv_bfloat16 lv = __float2bfloat16(v - __bfloat162float(hv));
        int kt = jg >> 4, kk = jg & 15;
        int la = ((row & 7) << 2) | ((kk >> 1) & 3);
        int rg = ((row >> 3) & 1) | ((kk >> 3) << 1);
        uint32_t off = (uint32_t)(kt * 512 + la * 16 + rg * 4 + (kk & 1) * 2);
        *(unsigned short*)(&g_ha[0][0][q][off]) = __bfloat16_as_ushort(hv);
        *(unsigned short*)(&g_ha[0][1][q][off]) = __bfloat16_as_ushort(lv);
    }
    asm volatile("fence.proxy.async;" ::: "memory");
    __syncthreads();

    // ---- preload B-hi fragments into registers (4 kt per warp) ----
    uint32_t bh[4][4][2];
    if (wid < NMW) {
#pragma unroll
        for (int nt = 0; nt < 4; nt++)
#pragma unroll
            for (int kt = 0; kt < 4; kt++) {
                uint32_t boff = smb + SM_W +
                    (uint32_t)(((nt * 64 + wid * 4 + kt) * 32 + lane) * 8);
                asm volatile("ld.shared.v2.u32 {%0,%1}, [%2];"
                    : "=r"(bh[nt][kt][0]), "=r"(bh[nt][kt][1]) : "r"(boff));
            }
    }

    // epilogue constants: thread o (0..511) handles 1 output
    const int eo = tid;                       // valid when wid < 16
    const int ent = eo >> 7;
    const int elane = (eo >> 2) & 31;
    const int ei = eo & 3;
    const int erow = (elane >> 2) + ((ei >> 1) << 3);
    const int ecol = ent * 8 + ((elane & 3) << 1) + (ei & 1);
    const int en0 = q * 16 + erow;
    const int ejg = jb + ecol;
    const int ebase = ent * 128 + elane * 4 + ei;
    const int ikt = ejg >> 4, ikk = ejg & 15;
    const int ila = ((erow & 7) << 2) | ((ikk >> 1) & 3);
    const int irg = ((erow >> 3) & 1) | ((ikk >> 3) << 1);
    const uint32_t ioff = (uint32_t)(ikt * 512 + ila * 16 + irg * 4 + (ikk & 1) * 2);

    for (int t = 1; t < TB; t++) {
        const uint32_t par = (uint32_t)((t - 1) & 1);
        if (wid == NMW) {
            // -------- control warp --------
            if (lane == 0) {
                asm volatile("fence.proxy.async;" ::: "memory");
                gbar((unsigned)t);
                const unsigned char* hs = &g_ha[(t - 1) & 1][0][q][0];
                const unsigned char* ls = &g_ha[(t - 1) & 1][1][q][0];
#pragma unroll
                for (int ch = 0; ch < 4; ch++) {
                    mbexpect(mb0 + ch * 8, 16384u);
                    bulkcp8k(smb + SM_A + ch * 8192,         hs + ch * 8192, mb0 + ch * 8);
                    bulkcp8k(smb + SM_A + 32768 + ch * 8192, ls + ch * 8192, mb0 + ch * 8);
                }
            }
            __syncthreads();   // reduce-sync
            __syncthreads();   // end-sync
        } else {
            // -------- mma warps (16): 4 kt each --------
            float u = g_ih[((size_t)en0 * TB + (t - 1)) * HB + ejg];

            float c[4][4];
#pragma unroll
            for (int nt = 0; nt < 4; nt++) { c[nt][0]=0.f; c[nt][1]=0.f; c[nt][2]=0.f; c[nt][3]=0.f; }

            mwait(mb0 + (wid >> 2) * 8, par);
            uint32_t aoff = smb + SM_A + (uint32_t)(wid * 4) * 512 + lane * 16;
#pragma unroll
            for (int kt = 0; kt < 4; kt++) {
                uint32_t ah[4], al[4];
                asm volatile("ld.shared.v4.u32 {%0,%1,%2,%3}, [%4];"
                    : "=r"(ah[0]), "=r"(ah[1]), "=r"(ah[2]), "=r"(ah[3]) : "r"(aoff));
                asm volatile("ld.shared.v4.u32 {%0,%1,%2,%3}, [%4];"
                    : "=r"(al[0]), "=r"(al[1]), "=r"(al[2]), "=r"(al[3]) : "r"(aoff + 32768u));
#pragma unroll
                for (int nt = 0; nt < 4; nt++) {
                    uint32_t bl0, bl1;
                    uint32_t bloff = smb + SM_W + 65536u +
                        (uint32_t)(((nt * 64 + wid * 4 + kt) * 32 + lane) * 8);
                    asm volatile("ld.shared.v2.u32 {%0,%1}, [%2];"
                        : "=r"(bl0), "=r"(bl1) : "r"(bloff));
                    mma16816(c[nt], ah, bh[nt][kt][0], bh[nt][kt][1]);  // hi*hi
                    mma16816(c[nt], al, bh[nt][kt][0], bh[nt][kt][1]);  // lo*hi
                    mma16816(c[nt], ah, bl0, bl1);                      // hi*lo
                }
                aoff += 512u;
            }
            {
                float* rp = red + wid * 512 + lane * 4;
#pragma unroll
                for (int nt = 0; nt < 4; nt++)
                    *(float4*)(rp + nt * 128) = make_float4(c[nt][0], c[nt][1], c[nt][2], c[nt][3]);
            }
            __syncthreads();   // reduce-sync

            // epilogue: 512 threads, 1 output each
            float s = 0.f;
#pragma unroll
            for (int w = 0; w < NMW; w++) s += red[w * 512 + ebase];
            float v = s + u;

            out[((size_t)en0 * TB + t) * HB + ejg] = v;
            if (two) out[NTH + ((size_t)en0 * TB + t) * HB + ejg] = v;

            __nv_bfloat16 hv = __float2bfloat16(v);
            __nv_bfloat16 lv = __float2bfloat16(v - __bfloat162float(hv));
            *(unsigned short*)(&g_ha[t & 1][0][q][ioff]) = __bfloat16_as_ushort(hv);
            *(unsigned short*)(&g_ha[t & 1][1][q][ioff]) = __bfloat16_as_ushort(lv);
            asm volatile("fence.proxy.async;" ::: "memory");
            __syncthreads();   // end-sync
        }
    }
}

// ---- launch ----
extern "C" void kernel_launch(void* const* d_in, const int* in_sizes, int n_in,
                              void* d_out, int out_size) {
    const float *x = nullptr, *initial = nullptr, *W_ih = nullptr, *b_ih = nullptr, *W_hh = nullptr;
    for (int i = 0; i < n_in; i++) {
        switch (in_sizes[i]) {
            case 5767168: x = (const float*)d_in[i]; break;
            case 65536:   initial = (const float*)d_in[i]; break;
            case 90112:   W_ih = (const float*)d_in[i]; break;
            case 1024:    b_ih = (const float*)d_in[i]; break;
            case 1048576: W_hh = (const float*)d_in[i]; break;
            default: break;
        }
    }
    float* out = (float*)d_out;
    const long long NTH = (long long)NB * TB * HB;
    int two = ((long long)out_size >= 2 * NTH) ? 1 : 0;

    const int IH_SMEM = (IB * 64 + IB * 128) * 4;
    cudaFuncSetAttribute(ih_kernel, cudaFuncAttributeMaxDynamicSharedMemorySize, IH_SMEM);
    cudaFuncSetAttribute(rnn_kernel, cudaFuncAttributeMaxDynamicSharedMemorySize, SM_TOT);

    dim3 g1(HB / 128, (NB * TB) / 64);
    ih_kernel<<<g1, 256, IH_SMEM>>>(x, W_ih, b_ih);   // also resets barrier state
    rnn_kernel<<<NCTA, RT2, SM_TOT>>>(initial, W_hh, out, two);
}

// round 15
// speedup vs baseline: 1.0234x; 1.0234x over previous
#include <cuda_runtime.h>
#include <cuda_fp16.h>
#include <cstdint>

#define NB 64
#define TB 1024
#define IB 88
#define HB 1024

#define NCTA 128        // 4 batch-quarters x 32 col-groups
#define RT2 288         // 8 mma warps + 1 control warp

// smem byte offsets
#define SM_W    0        // W hi frag-packed 64KB, then W lo 64KB
#define SM_A    131072   // A hi 32KB, A lo 32KB
#define SM_RED  196608   // 8 warps * 512 floats = 16KB
#define SM_MBAR 212992   // 4 chunk mbarriers
#define SM_TOT  213120

// device scratch
__device__ __align__(256)  float g_ih[(size_t)NB * TB * HB];
// A-operand images, mma-fragment order: [buf][hi/lo][quarter][ktile 64][lane 32][reg 4] u32
__device__ __align__(1024) unsigned char g_ha[2][2][4][32768];
__device__ unsigned g_arrive, g_epoch;

// ---- ptx helpers (baseline PTX only; no 'a' features) ----
__device__ __forceinline__ void mbinit(uint32_t m, uint32_t c) {
    asm volatile("mbarrier.init.shared.b64 [%0], %1;" :: "r"(m), "r"(c) : "memory");
}
__device__ __forceinline__ void mbexpect(uint32_t m, uint32_t b) {
    asm volatile("mbarrier.arrive.expect_tx.shared.b64 _, [%0], %1;" :: "r"(m), "r"(b) : "memory");
}
__device__ __forceinline__ void mwait(uint32_t m, uint32_t par) {
    asm volatile(
        "{\n\t.reg .pred P;\n"
        "W%=:\n\t"
        "mbarrier.try_wait.parity.shared::cta.b64 P, [%0], %1, 0x989680;\n\t"
        "@P bra D%=;\n\t"
        "bra W%=;\n"
        "D%=:\n\t}" :: "r"(m), "r"(par) : "memory");
}
__device__ __forceinline__ void bulkcp8k(uint32_t dst, const void* src, uint32_t mbar) {
    asm volatile(
        "cp.async.bulk.shared::cluster.global.mbarrier::complete_tx::bytes [%0], [%1], %2, [%3];"
        :: "r"(dst), "l"(src), "r"(8192u), "r"(mbar) : "memory");
}
__device__ __forceinline__ void gbar(unsigned b) {
    unsigned old;
    asm volatile("atom.release.gpu.global.add.u32 %0, [%1], 1;"
                 : "=r"(old) : "l"(&g_arrive) : "memory");
    if (old + 1u == b * (unsigned)NCTA) {
        asm volatile("st.release.gpu.global.u32 [%0], %1;" :: "l"(&g_epoch), "r"(b) : "memory");
    } else {
        unsigned e;
        do {
            asm volatile("ld.acquire.gpu.global.u32 %0, [%1];" : "=r"(e) : "l"(&g_epoch) : "memory");
        } while (e < b);
    }
}
// f32-accum fp16 mma (main term)
__device__ __forceinline__ void mma_f32(float c[4], const uint32_t a[4], uint32_t b0, uint32_t b1) {
    asm volatile(
        "mma.sync.aligned.m16n8k16.row.col.f32.f16.f16.f32 "
        "{%0,%1,%2,%3}, {%4,%5,%6,%7}, {%8,%9}, {%0,%1,%2,%3};"
        : "+f"(c[0]), "+f"(c[1]), "+f"(c[2]), "+f"(c[3])
        : "r"(a[0]), "r"(a[1]), "r"(a[2]), "r"(a[3]), "r"(b0), "r"(b1));
}
// f16-accum fp16 mma (correction terms); c = 2 b32 regs (4 halves, same element map)
__device__ __forceinline__ void mma_f16(uint32_t c[2], const uint32_t a[4], uint32_t b0, uint32_t b1) {
    asm volatile(
        "mma.sync.aligned.m16n8k16.row.col.f16.f16.f16.f16 "
        "{%0,%1}, {%2,%3,%4,%5}, {%6,%7}, {%0,%1};"
        : "+r"(c[0]), "+r"(c[1])
        : "r"(a[0]), "r"(a[1]), "r"(a[2]), "r"(a[3]), "r"(b0), "r"(b1));
}
__device__ __forceinline__ void split2h(float a, float b, uint32_t& hi, uint32_t& lo) {
    __half ha = __float2half_rn(a), hb = __float2half_rn(b);
    __half la = __float2half_rn(a - __half2float(ha));
    __half lb = __float2half_rn(b - __half2float(hb));
    hi = (uint32_t)__half_as_ushort(ha) | ((uint32_t)__half_as_ushort(hb) << 16);
    lo = (uint32_t)__half_as_ushort(la) | ((uint32_t)__half_as_ushort(lb) << 16);
}

// ---- kernel 1: ih = x @ W_ih^T + b (fp32 SIMT); also resets barrier state ----
__global__ __launch_bounds__(256) void ih_kernel(const float* __restrict__ x,
                                                 const float* __restrict__ W_ih,
                                                 const float* __restrict__ b_ih) {
    if (blockIdx.x == 0 && blockIdx.y == 0 && threadIdx.x == 0) {
        g_arrive = 0u; g_epoch = 0u;
    }
    extern __shared__ float smf[];
    float* xs = smf;
    float* wt = smf + IB * 64;
    const int jb = blockIdx.x * 128, mb = blockIdx.y * 64, tid = threadIdx.x;
    for (int e = tid; e < 64 * IB; e += 256) {
        int m = e / IB, i = e - m * IB;
        xs[i * 64 + m] = x[(size_t)(mb + m) * IB + i];
    }
    for (int e = tid; e < 128 * IB; e += 256) {
        int j = e / IB, i = e - j * IB;
        wt[i * 128 + j] = W_ih[(size_t)(jb + j) * IB + i];
    }
    __syncthreads();
    const int jo = (tid & 15) * 8, mo = (tid >> 4) * 4;
    float acc[4][8];
#pragma unroll
    for (int jj = 0; jj < 8; jj++) {
        float b = b_ih[jb + jo + jj];
        acc[0][jj] = b; acc[1][jj] = b; acc[2][jj] = b; acc[3][jj] = b;
    }
#pragma unroll 4
    for (int i = 0; i < IB; i++) {
        float4 xv = *(const float4*)&xs[i * 64 + mo];
        float4 w0 = *(const float4*)&wt[i * 128 + jo];
        float4 w1 = *(const float4*)&wt[i * 128 + jo + 4];
        float xm[4] = {xv.x, xv.y, xv.z, xv.w};
#pragma unroll
        for (int mm = 0; mm < 4; mm++) {
            acc[mm][0] += xm[mm] * w0.x; acc[mm][1] += xm[mm] * w0.y;
            acc[mm][2] += xm[mm] * w0.z; acc[mm][3] += xm[mm] * w0.w;
            acc[mm][4] += xm[mm] * w1.x; acc[mm][5] += xm[mm] * w1.y;
            acc[mm][6] += xm[mm] * w1.z; acc[mm][7] += xm[mm] * w1.w;
        }
    }
#pragma unroll
    for (int mm = 0; mm < 4; mm++) {
        size_t row = (size_t)(mb + mo + mm) * HB + jb + jo;
        *(float4*)&g_ih[row]     = make_float4(acc[mm][0], acc[mm][1], acc[mm][2], acc[mm][3]);
        *(float4*)&g_ih[row + 4] = make_float4(acc[mm][4], acc[mm][5], acc[mm][6], acc[mm][7]);
    }
}

// ---- persistent split-fp16 HMMA recurrence (R7 structure) ----
// hh term: f32-accum mma. lh + hl corrections: f16-accum mma (shared accumulator).
__global__ __launch_bounds__(RT2, 1)
void rnn_kernel(const float* __restrict__ initial, const float* __restrict__ W_hh,
                float* __restrict__ out, int two) {
    extern __shared__ __align__(1024) unsigned char sm[];
    const uint32_t smb = (uint32_t)__cvta_generic_to_shared(sm);
    const int tid = threadIdx.x, wid = tid >> 5, lane = tid & 31;
    const int bid = blockIdx.x;
    const int q = bid >> 5, g = bid & 31, jb = g * 32;
    float* red = (float*)(sm + SM_RED);
    const uint32_t mb0 = smb + SM_MBAR;
    const size_t NTH = (size_t)NB * TB * HB;

    if (tid == 0)
        for (int ch = 0; ch < 4; ch++) mbinit(mb0 + ch * 8, 1);

    // stage W slice, fragment-packed fp16 limbs (hi at SM_W, lo at +64KB)
    for (int e = tid; e < 32 * HB; e += RT2) {
        int n = e >> 10, k = e & (HB - 1);
        float w = W_hh[(size_t)(jb + n) * HB + k];
        __half hv = __float2half_rn(w);
        __half lv = __float2half_rn(w - __half2float(hv));
        int nt = n >> 3, nn = n & 7, kt = k >> 4, kk = k & 15;
        int lf = nn * 4 + ((kk >> 1) & 3);
        uint32_t off = (uint32_t)(((nt * 64 + kt) * 32 + lf) * 8 + (kk >> 3) * 4 + (kk & 1) * 2);
        *(unsigned short*)(sm + SM_W + off)         = __half_as_ushort(hv);
        *(unsigned short*)(sm + SM_W + 65536 + off) = __half_as_ushort(lv);
    }

    // ---- step 0: h0 = initial + ih[:,0]; emit out + A image buf0 ----
    for (int e = tid; e < 512; e += RT2) {
        int row = e >> 5, j = e & 31, jg = jb + j, n0 = q * 16 + row;
        float v = initial[(size_t)n0 * HB + jg] + g_ih[(size_t)n0 * TB * HB + jg];
        out[(size_t)n0 * TB * HB + jg] = v;
        if (two) out[NTH + (size_t)n0 * TB * HB + jg] = v;
        __half hv = __float2half_rn(v);
        __half lv = __float2half_rn(v - __half2float(hv));
        int kt = jg >> 4, kk = jg & 15;
        int la = ((row & 7) << 2) | ((kk >> 1) & 3);
        int rg = ((row >> 3) & 1) | ((kk >> 3) << 1);
        uint32_t off = (uint32_t)(kt * 512 + la * 16 + rg * 4 + (kk & 1) * 2);
        *(unsigned short*)(&g_ha[0][0][q][off]) = __half_as_ushort(hv);
        *(unsigned short*)(&g_ha[0][1][q][off]) = __half_as_ushort(lv);
    }
    asm volatile("fence.proxy.async;" ::: "memory");
    __syncthreads();

    // ---- preload B-hi fragments into registers (reused for all 1023 steps) ----
    uint32_t bh[4][8][2];
    if (wid < 8) {
#pragma unroll
        for (int nt = 0; nt < 4; nt++)
#pragma unroll
            for (int kt = 0; kt < 8; kt++) {
                uint32_t boff = smb + SM_W +
                    (uint32_t)(((nt * 64 + wid * 8 + kt) * 32 + lane) * 8);
                asm volatile("ld.shared.v2.u32 {%0,%1}, [%2];"
                    : "=r"(bh[nt][kt][0]), "=r"(bh[nt][kt][1]) : "r"(boff));
            }
    }

    // epilogue constants: thread j (0..255) handles outputs o = 2j, 2j+1
    const int ent = tid >> 6;
    const int elane = (tid >> 1) & 31;
    const int eip = tid & 1;
    const int erow = (elane >> 2) + eip * 8;
    const int ecol = ent * 8 + (elane & 3) * 2;
    const int en0 = q * 16 + erow;
    const int ejg = jb + ecol;
    const int ebase = ent * 128 + elane * 4 + 2 * eip;
    const int ikt = ejg >> 4, ikk = ejg & 15;
    const int ila = ((erow & 7) << 2) | ((ikk >> 1) & 3);
    const int irg = ((erow >> 3) & 1) | ((ikk >> 3) << 1);
    const uint32_t ioff = (uint32_t)(ikt * 512 + ila * 16 + irg * 4);

    for (int t = 1; t < TB; t++) {
        const uint32_t par = (uint32_t)((t - 1) & 1);
        if (wid == 8) {
            // -------- control warp --------
            if (lane == 0) {
                asm volatile("fence.proxy.async;" ::: "memory");
                gbar((unsigned)t);
                const unsigned char* hs = &g_ha[(t - 1) & 1][0][q][0];
                const unsigned char* ls = &g_ha[(t - 1) & 1][1][q][0];
#pragma unroll
                for (int ch = 0; ch < 4; ch++) {
                    mbexpect(mb0 + ch * 8, 16384u);
                    bulkcp8k(smb + SM_A + ch * 8192,         hs + ch * 8192, mb0 + ch * 8);
                    bulkcp8k(smb + SM_A + 32768 + ch * 8192, ls + ch * 8192, mb0 + ch * 8);
                }
            }
            __syncthreads();   // reduce-sync
            __syncthreads();   // end-sync
        } else {
            // -------- mma warps --------
            float2 u = *(const float2*)(g_ih + ((size_t)en0 * TB + (t - 1)) * HB + ejg);

            float chh[4][4];
            uint32_t cc[4][2];
#pragma unroll
            for (int nt = 0; nt < 4; nt++) {
                chh[nt][0]=0.f; chh[nt][1]=0.f; chh[nt][2]=0.f; chh[nt][3]=0.f;
                cc[nt][0] = 0u; cc[nt][1] = 0u;
            }

            mwait(mb0 + (wid >> 1) * 8, par);
            uint32_t aoff = smb + SM_A + (uint32_t)(wid * 8) * 512 + lane * 16;
#pragma unroll
            for (int kt = 0; kt < 8; kt++) {
                uint32_t ah[4], al[4];
                asm volatile("ld.shared.v4.u32 {%0,%1,%2,%3}, [%4];"
                    : "=r"(ah[0]), "=r"(ah[1]), "=r"(ah[2]), "=r"(ah[3]) : "r"(aoff));
                asm volatile("ld.shared.v4.u32 {%0,%1,%2,%3}, [%4];"
                    : "=r"(al[0]), "=r"(al[1]), "=r"(al[2]), "=r"(al[3]) : "r"(aoff + 32768u));
#pragma unroll
                for (int nt = 0; nt < 4; nt++) {
                    uint32_t bl0, bl1;
                    uint32_t bloff = smb + SM_W + 65536u +
                        (uint32_t)(((nt * 64 + wid * 8 + kt) * 32 + lane) * 8);
                    asm volatile("ld.shared.v2.u32 {%0,%1}, [%2];"
                        : "=r"(bl0), "=r"(bl1) : "r"(bloff));
                    mma_f32(chh[nt], ah, bh[nt][kt][0], bh[nt][kt][1]);  // hi*hi (f32 accum)
                    mma_f16(cc[nt],  al, bh[nt][kt][0], bh[nt][kt][1]);  // lo*hi (f16 accum)
                    mma_f16(cc[nt],  ah, bl0, bl1);                      // hi*lo (f16 accum)
                }
                aoff += 512u;
            }
            {
                float* rp = red + wid * 512 + lane * 4;
#pragma unroll
                for (int nt = 0; nt < 4; nt++) {
                    float2 c01 = __half22float2(*(__half2*)&cc[nt][0]);
                    float2 c23 = __half22float2(*(__half2*)&cc[nt][1]);
                    *(float4*)(rp + nt * 128) = make_float4(chh[nt][0] + c01.x,
                                                            chh[nt][1] + c01.y,
                                                            chh[nt][2] + c23.x,
                                                            chh[nt][3] + c23.y);
                }
            }
            __syncthreads();   // reduce-sync

            // epilogue: 256 threads, 2 outputs each
            float s0 = 0.f, s1 = 0.f;
#pragma unroll
            for (int w = 0; w < 8; w++) {
                s0 += red[w * 512 + ebase];
                s1 += red[w * 512 + ebase + 1];
            }
            float v0 = s0 + u.x, v1 = s1 + u.y;

            float* ob = out + ((size_t)en0 * TB + t) * HB + ejg;
            *(float2*)ob = make_float2(v0, v1);
            if (two) *(float2*)(ob + NTH) = make_float2(v0, v1);

            uint32_t hp, lp;
            split2h(v0, v1, hp, lp);
            *(uint32_t*)(&g_ha[t & 1][0][q][ioff]) = hp;
            *(uint32_t*)(&g_ha[t & 1][1][q][ioff]) = lp;
            asm volatile("fence.proxy.async;" ::: "memory");
            __syncthreads();   // end-sync
        }
    }
}

// ---- launch ----
extern "C" void kernel_launch(void* const* d_in, const int* in_sizes, int n_in,
                              void* d_out, int out_size) {
    const float *x = nullptr, *initial = nullptr, *W_ih = nullptr, *b_ih = nullptr, *W_hh = nullptr;
    for (int i = 0; i < n_in; i++) {
        switch (in_sizes[i]) {
            case 5767168: x = (const float*)d_in[i]; break;
            case 65536:   initial = (const float*)d_in[i]; break;
            case 90112:   W_ih = (const float*)d_in[i]; break;
            case 1024:    b_ih = (const float*)d_in[i]; break;
            case 1048576: W_hh = (const float*)d_in[i]; break;
            default: break;
        }
    }
    float* out = (float*)d_out;
    const long long NTH = (long long)NB * TB * HB;
    int two = ((long long)out_size >= 2 * NTH) ? 1 : 0;

    const int IH_SMEM = (IB * 64 + IB * 128) * 4;
    cudaFuncSetAttribute(ih_kernel, cudaFuncAttributeMaxDynamicSharedMemorySize, IH_SMEM);
    cudaFuncSetAttribute(rnn_kernel, cudaFuncAttributeMaxDynamicSharedMemorySize, SM_TOT);

    dim3 g1(HB / 128, (NB * TB) / 64);
    ih_kernel<<<g1, 256, IH_SMEM>>>(x, W_ih, b_ih);   // also resets barrier state
    rnn_kernel<<<NCTA, RT2, SM_TOT>>>(initial, W_hh, out, two);
}

// round 16
// speedup vs baseline: 1.1048x; 1.0795x over previous
#include <cuda_runtime.h>
#include <cuda_fp16.h>
#include <cstdint>

#define NB 64
#define TB 1024
#define IB 88
#define HB 1024

#define NCTA 128        // 4 batch-quarters x 32 col-groups
#define RT2 288         // 8 mma warps + 1 control warp

// smem byte offsets
#define SM_W    0        // W hi frag-packed 64KB, then W lo 64KB
#define SM_A    131072   // A hi 32KB (single limb)
#define SM_RED  163840   // 8 warps * 512 floats = 16KB
#define SM_MBAR 180224   // 4 chunk mbarriers
#define SM_TOT  180288

// device scratch
__device__ __align__(256)  float g_ih[(size_t)NB * TB * HB];
// A-operand images (hi limb only), mma-fragment order:
// [buf][quarter][ktile 64][lane 32][reg 4] u32
__device__ __align__(1024) unsigned char g_ha[2][4][32768];
__device__ unsigned g_arrive, g_epoch;

// ---- ptx helpers (baseline PTX only; no 'a' features) ----
__device__ __forceinline__ void mbinit(uint32_t m, uint32_t c) {
    asm volatile("mbarrier.init.shared.b64 [%0], %1;" :: "r"(m), "r"(c) : "memory");
}
__device__ __forceinline__ void mbexpect(uint32_t m, uint32_t b) {
    asm volatile("mbarrier.arrive.expect_tx.shared.b64 _, [%0], %1;" :: "r"(m), "r"(b) : "memory");
}
__device__ __forceinline__ void mwait(uint32_t m, uint32_t par) {
    asm volatile(
        "{\n\t.reg .pred P;\n"
        "W%=:\n\t"
        "mbarrier.try_wait.parity.shared::cta.b64 P, [%0], %1, 0x989680;\n\t"
        "@P bra D%=;\n\t"
        "bra W%=;\n"
        "D%=:\n\t}" :: "r"(m), "r"(par) : "memory");
}
__device__ __forceinline__ void bulkcp8k(uint32_t dst, const void* src, uint32_t mbar) {
    asm volatile(
        "cp.async.bulk.shared::cluster.global.mbarrier::complete_tx::bytes [%0], [%1], %2, [%3];"
        :: "r"(dst), "l"(src), "r"(8192u), "r"(mbar) : "memory");
}
__device__ __forceinline__ void gbar(unsigned b) {
    unsigned old;
    asm volatile("atom.release.gpu.global.add.u32 %0, [%1], 1;"
                 : "=r"(old) : "l"(&g_arrive) : "memory");
    if (old + 1u == b * (unsigned)NCTA) {
        asm volatile("st.release.gpu.global.u32 [%0], %1;" :: "l"(&g_epoch), "r"(b) : "memory");
    } else {
        unsigned e;
        do {
            asm volatile("ld.acquire.gpu.global.u32 %0, [%1];" : "=r"(e) : "l"(&g_epoch) : "memory");
        } while (e < b);
    }
}
__device__ __forceinline__ void mma_f32(float c[4], const uint32_t a[4], uint32_t b0, uint32_t b1) {
    asm volatile(
        "mma.sync.aligned.m16n8k16.row.col.f32.f16.f16.f32 "
        "{%0,%1,%2,%3}, {%4,%5,%6,%7}, {%8,%9}, {%0,%1,%2,%3};"
        : "+f"(c[0]), "+f"(c[1]), "+f"(c[2]), "+f"(c[3])
        : "r"(a[0]), "r"(a[1]), "r"(a[2]), "r"(a[3]), "r"(b0), "r"(b1));
}

// ---- kernel 1: ih = x @ W_ih^T + b (fp32 SIMT); also resets barrier state ----
__global__ __launch_bounds__(256) void ih_kernel(const float* __restrict__ x,
                                                 const float* __restrict__ W_ih,
                                                 const float* __restrict__ b_ih) {
    if (blockIdx.x == 0 && blockIdx.y == 0 && threadIdx.x == 0) {
        g_arrive = 0u; g_epoch = 0u;
    }
    extern __shared__ float smf[];
    float* xs = smf;
    float* wt = smf + IB * 64;
    const int jb = blockIdx.x * 128, mb = blockIdx.y * 64, tid = threadIdx.x;
    for (int e = tid; e < 64 * IB; e += 256) {
        int m = e / IB, i = e - m * IB;
        xs[i * 64 + m] = x[(size_t)(mb + m) * IB + i];
    }
    for (int e = tid; e < 128 * IB; e += 256) {
        int j = e / IB, i = e - j * IB;
        wt[i * 128 + j] = W_ih[(size_t)(jb + j) * IB + i];
    }
    __syncthreads();
    const int jo = (tid & 15) * 8, mo = (tid >> 4) * 4;
    float acc[4][8];
#pragma unroll
    for (int jj = 0; jj < 8; jj++) {
        float b = b_ih[jb + jo + jj];
        acc[0][jj] = b; acc[1][jj] = b; acc[2][jj] = b; acc[3][jj] = b;
    }
#pragma unroll 4
    for (int i = 0; i < IB; i++) {
        float4 xv = *(const float4*)&xs[i * 64 + mo];
        float4 w0 = *(const float4*)&wt[i * 128 + jo];
        float4 w1 = *(const float4*)&wt[i * 128 + jo + 4];
        float xm[4] = {xv.x, xv.y, xv.z, xv.w};
#pragma unroll
        for (int mm = 0; mm < 4; mm++) {
            acc[mm][0] += xm[mm] * w0.x; acc[mm][1] += xm[mm] * w0.y;
            acc[mm][2] += xm[mm] * w0.z; acc[mm][3] += xm[mm] * w0.w;
            acc[mm][4] += xm[mm] * w1.x; acc[mm][5] += xm[mm] * w1.y;
            acc[mm][6] += xm[mm] * w1.z; acc[mm][7] += xm[mm] * w1.w;
        }
    }
#pragma unroll
    for (int mm = 0; mm < 4; mm++) {
        size_t row = (size_t)(mb + mo + mm) * HB + jb + jo;
        *(float4*)&g_ih[row]     = make_float4(acc[mm][0], acc[mm][1], acc[mm][2], acc[mm][3]);
        *(float4*)&g_ih[row + 4] = make_float4(acc[mm][4], acc[mm][5], acc[mm][6], acc[mm][7]);
    }
}

// ---- persistent 2-term split-fp16 HMMA recurrence (R7 structure) ----
// CTA (q,g): batch rows q*16..+15, hidden cols g*32..+31.
// Warp w (<8) owns kt in [8w, 8w+8) x ALL 4 n-tiles.
// Terms: W_hi*h_hi + W_lo*h_hi  (h_lo dropped; h->fp16 rounding per step ~2^-12)
// B-hi in registers; B-lo from smem; A (hi limb only) staged by bulk copy.
__global__ __launch_bounds__(RT2, 1)
void rnn_kernel(const float* __restrict__ initial, const float* __restrict__ W_hh,
                float* __restrict__ out, int two) {
    extern __shared__ __align__(1024) unsigned char sm[];
    const uint32_t smb = (uint32_t)__cvta_generic_to_shared(sm);
    const int tid = threadIdx.x, wid = tid >> 5, lane = tid & 31;
    const int bid = blockIdx.x;
    const int q = bid >> 5, g = bid & 31, jb = g * 32;
    float* red = (float*)(sm + SM_RED);
    const uint32_t mb0 = smb + SM_MBAR;
    const size_t NTH = (size_t)NB * TB * HB;

    if (tid == 0)
        for (int ch = 0; ch < 4; ch++) mbinit(mb0 + ch * 8, 1);

    // stage W slice, fragment-packed fp16 limbs (hi at SM_W, lo at +64KB)
    for (int e = tid; e < 32 * HB; e += RT2) {
        int n = e >> 10, k = e & (HB - 1);
        float w = W_hh[(size_t)(jb + n) * HB + k];
        __half hv = __float2half_rn(w);
        __half lv = __float2half_rn(w - __half2float(hv));
        int nt = n >> 3, nn = n & 7, kt = k >> 4, kk = k & 15;
        int lf = nn * 4 + ((kk >> 1) & 3);
        uint32_t off = (uint32_t)(((nt * 64 + kt) * 32 + lf) * 8 + (kk >> 3) * 4 + (kk & 1) * 2);
        *(unsigned short*)(sm + SM_W + off)         = __half_as_ushort(hv);
        *(unsigned short*)(sm + SM_W + 65536 + off) = __half_as_ushort(lv);
    }

    // ---- step 0: h0 = initial + ih[:,0]; emit out + A image buf0 (hi only) ----
    for (int e = tid; e < 512; e += RT2) {
        int row = e >> 5, j = e & 31, jg = jb + j, n0 = q * 16 + row;
        float v = initial[(size_t)n0 * HB + jg] + g_ih[(size_t)n0 * TB * HB + jg];
        out[(size_t)n0 * TB * HB + jg] = v;
        if (two) out[NTH + (size_t)n0 * TB * HB + jg] = v;
        __half hv = __float2half_rn(v);
        int kt = jg >> 4, kk = jg & 15;
        int la = ((row & 7) << 2) | ((kk >> 1) & 3);
        int rg = ((row >> 3) & 1) | ((kk >> 3) << 1);
        uint32_t off = (uint32_t)(kt * 512 + la * 16 + rg * 4 + (kk & 1) * 2);
        *(unsigned short*)(&g_ha[0][q][off]) = __half_as_ushort(hv);
    }
    asm volatile("fence.proxy.async;" ::: "memory");
    __syncthreads();

    // ---- preload B-hi fragments into registers (reused for all 1023 steps) ----
    uint32_t bh[4][8][2];
    if (wid < 8) {
#pragma unroll
        for (int nt = 0; nt < 4; nt++)
#pragma unroll
            for (int kt = 0; kt < 8; kt++) {
                uint32_t boff = smb + SM_W +
                    (uint32_t)(((nt * 64 + wid * 8 + kt) * 32 + lane) * 8);
                asm volatile("ld.shared.v2.u32 {%0,%1}, [%2];"
                    : "=r"(bh[nt][kt][0]), "=r"(bh[nt][kt][1]) : "r"(boff));
            }
    }

    // epilogue constants: thread j (0..255) handles outputs o = 2j, 2j+1
    const int ent = tid >> 6;
    const int elane = (tid >> 1) & 31;
    const int eip = tid & 1;
    const int erow = (elane >> 2) + eip * 8;
    const int ecol = ent * 8 + (elane & 3) * 2;
    const int en0 = q * 16 + erow;
    const int ejg = jb + ecol;
    const int ebase = ent * 128 + elane * 4 + 2 * eip;
    const int ikt = ejg >> 4, ikk = ejg & 15;
    const int ila = ((erow & 7) << 2) | ((ikk >> 1) & 3);
    const int irg = ((erow >> 3) & 1) | ((ikk >> 3) << 1);
    const uint32_t ioff = (uint32_t)(ikt * 512 + ila * 16 + irg * 4);

    for (int t = 1; t < TB; t++) {
        const uint32_t par = (uint32_t)((t - 1) & 1);
        if (wid == 8) {
            // -------- control warp --------
            if (lane == 0) {
                asm volatile("fence.proxy.async;" ::: "memory");
                gbar((unsigned)t);
                const unsigned char* hs = &g_ha[(t - 1) & 1][q][0];
#pragma unroll
                for (int ch = 0; ch < 4; ch++) {
                    mbexpect(mb0 + ch * 8, 8192u);
                    bulkcp8k(smb + SM_A + ch * 8192, hs + ch * 8192, mb0 + ch * 8);
                }
            }
            __syncthreads();   // reduce-sync
            __syncthreads();   // end-sync
        } else {
            // -------- mma warps: 2 MMAs per (nt,kt) --------
            float2 u = *(const float2*)(g_ih + ((size_t)en0 * TB + (t - 1)) * HB + ejg);

            float c[4][4];
#pragma unroll
            for (int nt = 0; nt < 4; nt++) { c[nt][0]=0.f; c[nt][1]=0.f; c[nt][2]=0.f; c[nt][3]=0.f; }

            mwait(mb0 + (wid >> 1) * 8, par);
            uint32_t aoff = smb + SM_A + (uint32_t)(wid * 8) * 512 + lane * 16;
#pragma unroll
            for (int kt = 0; kt < 8; kt++) {
                uint32_t ah[4];
                asm volatile("ld.shared.v4.u32 {%0,%1,%2,%3}, [%4];"
                    : "=r"(ah[0]), "=r"(ah[1]), "=r"(ah[2]), "=r"(ah[3]) : "r"(aoff));
#pragma unroll
                for (int nt = 0; nt < 4; nt++) {
                    uint32_t bl0, bl1;
                    uint32_t bloff = smb + SM_W + 65536u +
                        (uint32_t)(((nt * 64 + wid * 8 + kt) * 32 + lane) * 8);
                    asm volatile("ld.shared.v2.u32 {%0,%1}, [%2];"
                        : "=r"(bl0), "=r"(bl1) : "r"(bloff));
                    mma_f32(c[nt], ah, bh[nt][kt][0], bh[nt][kt][1]);  // hi*hi
                    mma_f32(c[nt], ah, bl0, bl1);                      // lo*hi
                }
                aoff += 512u;
            }
            {
                float* rp = red + wid * 512 + lane * 4;
#pragma unroll
                for (int nt = 0; nt < 4; nt++)
                    *(float4*)(rp + nt * 128) = make_float4(c[nt][0], c[nt][1], c[nt][2], c[nt][3]);
            }
            __syncthreads();   // reduce-sync

            // epilogue: 256 threads, 2 outputs each
            float s0 = 0.f, s1 = 0.f;
#pragma unroll
            for (int w = 0; w < 8; w++) {
                s0 += red[w * 512 + ebase];
                s1 += red[w * 512 + ebase + 1];
            }
            float v0 = s0 + u.x, v1 = s1 + u.y;

            float* ob = out + ((size_t)en0 * TB + t) * HB + ejg;
            *(float2*)ob = make_float2(v0, v1);
            if (two) *(float2*)(ob + NTH) = make_float2(v0, v1);

            uint32_t hp = (uint32_t)__half_as_ushort(__float2half_rn(v0)) |
                          ((uint32_t)__half_as_ushort(__float2half_rn(v1)) << 16);
            *(uint32_t*)(&g_ha[t & 1][q][ioff]) = hp;
            asm volatile("fence.proxy.async;" ::: "memory");
            __syncthreads();   // end-sync
        }
    }
}

// ---- launch ----
extern "C" void kernel_launch(void* const* d_in, const int* in_sizes, int n_in,
                              void* d_out, int out_size) {
    const float *x = nullptr, *initial = nullptr, *W_ih = nullptr, *b_ih = nullptr, *W_hh = nullptr;
    for (int i = 0; i < n_in; i++) {
        switch (in_sizes[i]) {
            case 5767168: x = (const float*)d_in[i]; break;
            case 65536:   initial = (const float*)d_in[i]; break;
            case 90112:   W_ih = (const float*)d_in[i]; break;
            case 1024:    b_ih = (const float*)d_in[i]; break;
            case 1048576: W_hh = (const float*)d_in[i]; break;
            default: break;
        }
    }
    float* out = (float*)d_out;
    const long long NTH = (long long)NB * TB * HB;
    int two = ((long long)out_size >= 2 * NTH) ? 1 : 0;

    const int IH_SMEM = (IB * 64 + IB * 128) * 4;
    cudaFuncSetAttribute(ih_kernel, cudaFuncAttributeMaxDynamicSharedMemorySize, IH_SMEM);
    cudaFuncSetAttribute(rnn_kernel, cudaFuncAttributeMaxDynamicSharedMemorySize, SM_TOT);

    dim3 g1(HB / 128, (NB * TB) / 64);
    ih_kernel<<<g1, 256, IH_SMEM>>>(x, W_ih, b_ih);   // also resets barrier state
    rnn_kernel<<<NCTA, RT2, SM_TOT>>>(initial, W_hh, out, two);
}